// round 3
// baseline (speedup 1.0000x reference)
#include <cuda_runtime.h>
#include <cuda_bf16.h>
#include <math.h>

#define NN    50000
#define EE    800000
#define DIN   300
#define DH    96
#define DOUT  2
#define GG    64

// packed fp32x2 FMA: two independent fp32 FMAs in one instruction (sm_10x).
#define FMA_F32X2(acc, a, b) \
    asm("fma.rn.f32x2 %0, %1, %2, %0;" : "+l"(acc) : "l"(a), "l"(b))
#define PACK_BCAST(dst, v) \
    asm("mov.b64 %0, {%1, %1};" : "=l"(dst) : "r"(__float_as_uint(v)))
#define UNPACK2(lo, hi, p) \
    asm("mov.b64 {%0, %1}, %2;" : "=f"(lo), "=f"(hi) : "l"(p))

// ---------------- scratch (device globals; no allocation allowed) -----------
__device__ float g_dis[NN];                 // deg -> deg_inv_sqrt (in place)
__device__ float g_h  [(size_t)NN * DH];    // transformed features
__device__ float g_agg[(size_t)NN * DH];    // aggregation buffer
__device__ float g_pool[GG * DH];
__device__ float g_cnt [GG];

// ---------------- degree ----------------------------------------------------
__global__ void k_deg_init() {
    int i = blockIdx.x * blockDim.x + threadIdx.x;
    if (i < NN) g_dis[i] = 1.0f;            // +1 self loop
}
__global__ void k_deg_count(const int* __restrict__ dst) {
    int e = blockIdx.x * blockDim.x + threadIdx.x;
    if (e < EE) atomicAdd(&g_dis[dst[e]], 1.0f);
}
__global__ void k_deg_finish() {
    int i = blockIdx.x * blockDim.x + threadIdx.x;
    if (i < NN) g_dis[i] = rsqrtf(g_dis[i]);
    if (i < GG * DH) g_pool[i] = 0.0f;
    if (i < GG)      g_cnt[i]  = 0.0f;
}

// ---------------- SGEMM: out = in @ W, BM=128 BN=96 BK=16, 192 thr ----------
// 8x8 micro-tile per thread, accumulators packed as f32x2 column pairs.
// Epilogue: g_h = acc, g_agg = acc * dis^2 (self-loop init).
// IN_IS_AGG: read from device-global g_agg (layer 2). RELU_BIAS: relu(in+b[k]).
template <int K, bool RELU_BIAS, bool IN_IS_AGG>
__global__ void __launch_bounds__(192, 2)
k_gemm(const float* __restrict__ in, const float* __restrict__ W,
       const float* __restrict__ bias)
{
    __shared__ float xs[16 * 132];      // [kk][row 0..127], stride 132
    __shared__ float ws[16 * 96];       // [kk][col]
    __shared__ float bs[DH];

    const int tid = threadIdx.x;
    const int ty  = tid / 12;           // 0..15 -> 8 rows each
    const int tx  = tid % 12;           // 0..11 -> 8 cols each
    const int r0  = blockIdx.x * 128;

    const float* __restrict__ src_in = IN_IS_AGG ? (const float*)g_agg : in;

    if (RELU_BIAS) { if (tid < DH) bs[tid] = bias[tid]; }

    unsigned long long acc[8][4];       // [row][colpair] f32x2
#pragma unroll
    for (int i = 0; i < 8; i++)
#pragma unroll
        for (int j = 0; j < 4; j++) acc[i][j] = 0ull;

    const int nstage = (K + 15) / 16;
    for (int s = 0; s < nstage; s++) {
        const int k0 = s * 16;
        __syncthreads();
        if (k0 + 16 <= K) {
            // full stage: vectorized loads
            // x tile: 128 rows x 16 k = 512 float4
            for (int idx = tid; idx < 512; idx += 192) {
                int row = idx >> 2, q = idx & 3;
                int gr = r0 + row;
                float4 v = make_float4(0.f, 0.f, 0.f, 0.f);
                if (gr < NN)
                    v = *reinterpret_cast<const float4*>(src_in + (size_t)gr * K + k0 + q * 4);
                if (RELU_BIAS) {
                    v.x = fmaxf(v.x + bs[k0 + q * 4 + 0], 0.f);
                    v.y = fmaxf(v.y + bs[k0 + q * 4 + 1], 0.f);
                    v.z = fmaxf(v.z + bs[k0 + q * 4 + 2], 0.f);
                    v.w = fmaxf(v.w + bs[k0 + q * 4 + 3], 0.f);
                }
                xs[(q * 4 + 0) * 132 + row] = v.x;
                xs[(q * 4 + 1) * 132 + row] = v.y;
                xs[(q * 4 + 2) * 132 + row] = v.z;
                xs[(q * 4 + 3) * 132 + row] = v.w;
            }
            // W tile: 16 x 96 = 384 float4
            for (int idx = tid; idx < 384; idx += 192) {
                int kk = idx / 24, c4 = idx % 24;
                *reinterpret_cast<float4*>(&ws[kk * 96 + c4 * 4]) =
                    *reinterpret_cast<const float4*>(W + (size_t)(k0 + kk) * 96 + c4 * 4);
            }
        } else {
            // tail stage (only K=300 path; no relu-bias there)
            for (int idx = tid; idx < 128 * 16; idx += 192) {
                int row = idx >> 4, kk = idx & 15;
                int gr = r0 + row, gk = k0 + kk;
                float v = 0.f;
                if (gr < NN && gk < K) v = src_in[(size_t)gr * K + gk];
                xs[kk * 132 + row] = v;
            }
            for (int idx = tid; idx < 16 * 96; idx += 192) {
                int kk = idx / 96, col = idx % 96;
                int gk = k0 + kk;
                ws[kk * 96 + col] = (gk < K) ? W[(size_t)gk * 96 + col] : 0.f;
            }
        }
        __syncthreads();

#pragma unroll
        for (int kk = 0; kk < 16; kk++) {
            // a: 8 rows (two LDS.128)
            float4 a0 = *reinterpret_cast<const float4*>(&xs[kk * 132 + ty * 8]);
            float4 a1 = *reinterpret_cast<const float4*>(&xs[kk * 132 + ty * 8 + 4]);
            unsigned long long ab[8];
            PACK_BCAST(ab[0], a0.x); PACK_BCAST(ab[1], a0.y);
            PACK_BCAST(ab[2], a0.z); PACK_BCAST(ab[3], a0.w);
            PACK_BCAST(ab[4], a1.x); PACK_BCAST(ab[5], a1.y);
            PACK_BCAST(ab[6], a1.z); PACK_BCAST(ab[7], a1.w);
            // b: 4 column pairs (LDS.64 each)
            unsigned long long bp[4];
#pragma unroll
            for (int j = 0; j < 4; j++)
                bp[j] = *reinterpret_cast<const unsigned long long*>(
                            &ws[kk * 96 + tx * 8 + j * 2]);
#pragma unroll
            for (int i = 0; i < 8; i++)
#pragma unroll
                for (int j = 0; j < 4; j++)
                    FMA_F32X2(acc[i][j], ab[i], bp[j]);
        }
    }

    // epilogue: unpack, write g_h and g_agg (= acc * dis^2)
#pragma unroll
    for (int i = 0; i < 8; i++) {
        int r = r0 + ty * 8 + i;
        if (r >= NN) continue;
        float ds = g_dis[r];
        float d2 = ds * ds;
        float v[8];
        UNPACK2(v[0], v[1], acc[i][0]);
        UNPACK2(v[2], v[3], acc[i][1]);
        UNPACK2(v[4], v[5], acc[i][2]);
        UNPACK2(v[6], v[7], acc[i][3]);
        size_t o = (size_t)r * 96 + tx * 8;
        *reinterpret_cast<float4*>(g_h + o)     = make_float4(v[0], v[1], v[2], v[3]);
        *reinterpret_cast<float4*>(g_h + o + 4) = make_float4(v[4], v[5], v[6], v[7]);
        *reinterpret_cast<float4*>(g_agg + o)     =
            make_float4(v[0] * d2, v[1] * d2, v[2] * d2, v[3] * d2);
        *reinterpret_cast<float4*>(g_agg + o + 4) =
            make_float4(v[4] * d2, v[5] * d2, v[6] * d2, v[7] * d2);
    }
}

// ---------------- edge scatter: agg[dst] += h[src] * dis[src]*dis[dst] ------
__global__ void __launch_bounds__(192)
k_scatter(const int* __restrict__ src, const int* __restrict__ dst)
{
    int e = blockIdx.x * 8 + threadIdx.y;
    if (e >= EE) return;
    int s = src[e], d = dst[e];
    float nrm = g_dis[s] * g_dis[d];
    int c = threadIdx.x * 4;
    float4 v = *reinterpret_cast<const float4*>(g_h + (size_t)s * 96 + c);
    float4 m = make_float4(v.x * nrm, v.y * nrm, v.z * nrm, v.w * nrm);
    float* p = g_agg + (size_t)d * 96 + c;
    asm volatile("red.global.add.v4.f32 [%0], {%1, %2, %3, %4};"
                 :: "l"(__cvta_generic_to_global(p)),
                    "f"(m.x), "f"(m.y), "f"(m.z), "f"(m.w) : "memory");
}

// ---------------- pooling ----------------------------------------------------
__global__ void __launch_bounds__(96)
k_pool(const float* __restrict__ b2, const int* __restrict__ batch)
{
    int c  = threadIdx.x;
    int r0 = blockIdx.x * 64;
    int re = min(r0 + 64, NN);
    if (r0 >= NN) return;
    float bb = b2[c];
    float acc = 0.0f;
    int cur = batch[r0];
    int run = 0;
    for (int r = r0; r < re; r++) {
        int g = batch[r];
        if (g != cur) {
            atomicAdd(&g_pool[cur * DH + c], acc);
            if (c == 0) atomicAdd(&g_cnt[cur], (float)run);
            acc = 0.0f; run = 0; cur = g;
        }
        acc += fmaxf(g_agg[(size_t)r * 96 + c] + bb, 0.0f);
        run++;
    }
    atomicAdd(&g_pool[cur * DH + c], acc);
    if (c == 0) atomicAdd(&g_cnt[cur], (float)run);
}

// ---------------- head -------------------------------------------------------
__global__ void k_fc(const float* __restrict__ Wfc, const float* __restrict__ bfc,
                     float* __restrict__ out)
{
    int t = threadIdx.x;
    if (t >= GG * DOUT) return;
    int g = t >> 1, o = t & 1;
    float cn = fmaxf(g_cnt[g], 1.0f);
    float s = bfc[o];
    for (int c = 0; c < DH; c++)
        s += (g_pool[g * DH + c] / cn) * Wfc[c * DOUT + o];
    out[g * DOUT + o] = s;
}

// ---------------- launch ------------------------------------------------------
extern "C" void kernel_launch(void* const* d_in, const int* in_sizes, int n_in,
                              void* d_out, int out_size)
{
    const float* x    = (const float*)d_in[0];
    const float* W1   = (const float*)d_in[1];
    const float* b1   = (const float*)d_in[2];
    const float* W2   = (const float*)d_in[3];
    const float* b2   = (const float*)d_in[4];
    const float* Wfc  = (const float*)d_in[5];
    const float* bfc  = (const float*)d_in[6];
    const int*   src  = (const int*)d_in[7];
    const int*   dst  = (const int*)d_in[8];
    const int*   batch= (const int*)d_in[9];
    float* out = (float*)d_out;

    const int nb_n = (NN + 255) / 256;
    const int nb_e = (EE + 255) / 256;
    const int nb_g = (NN + 127) / 128;
    const int nb_p = (NN + 63) / 64;

    k_deg_init  <<<nb_n, 256>>>();
    k_deg_count <<<nb_e, 256>>>(dst);
    k_deg_finish<<<nb_n, 256>>>();

    // layer 1: h1 = x@W1; agg1 = h1*dis^2
    k_gemm<DIN, false, false><<<nb_g, 192>>>(x, W1, b1);
    k_scatter<<<(EE + 7) / 8, dim3(24, 8)>>>(src, dst);

    // layer 2: h2 = relu(agg1+b1)@W2; agg2 = h2*dis^2
    k_gemm<DH, true, true><<<nb_g, 192>>>(nullptr, W2, b1);
    k_scatter<<<(EE + 7) / 8, dim3(24, 8)>>>(src, dst);

    k_pool<<<nb_p, 96>>>(b2, batch);
    k_fc  <<<1, 128>>>(Wfc, bfc, out);
}

// round 4
// speedup vs baseline: 1.2447x; 1.2447x over previous
#include <cuda_runtime.h>
#include <cuda_bf16.h>
#include <math.h>

#define NN    50000
#define EE    800000
#define DIN   300
#define DH    96
#define DOUT  2
#define GG    64

// ---------------- scratch (device globals; no allocation allowed) -----------
__device__ float g_dis[NN];                 // deg -> deg_inv_sqrt (in place)
__device__ float g_h  [(size_t)NN * DH];    // transformed features
__device__ float g_agg[(size_t)NN * DH];    // aggregation buffer
__device__ float g_pool[GG * DH];
__device__ float g_cnt [GG];

// ---------------- degree ----------------------------------------------------
__global__ void k_deg_init() {
    int i = blockIdx.x * blockDim.x + threadIdx.x;
    if (i < NN) g_dis[i] = 1.0f;            // +1 self loop
}
__global__ void k_deg_count(const int* __restrict__ dst) {
    int e = blockIdx.x * blockDim.x + threadIdx.x;
    if (e < EE) atomicAdd(&g_dis[dst[e]], 1.0f);
}
__global__ void k_deg_finish() {
    int i = blockIdx.x * blockDim.x + threadIdx.x;
    if (i < NN) g_dis[i] = rsqrtf(g_dis[i]);
    if (i < GG * DH) g_pool[i] = 0.0f;
    if (i < GG)      g_cnt[i]  = 0.0f;
}

// ---------------- mma helpers ------------------------------------------------
__device__ __forceinline__ unsigned smem_u32(const void* p) {
    return (unsigned)__cvta_generic_to_shared(p);
}
#define LDSM_X4(r, addr) \
    asm volatile("ldmatrix.sync.aligned.m8n8.x4.shared.b16 {%0,%1,%2,%3},[%4];" \
                 : "=r"((r)[0]), "=r"((r)[1]), "=r"((r)[2]), "=r"((r)[3]) : "r"(addr))
#define LDSM_X2_T(r, addr) \
    asm volatile("ldmatrix.sync.aligned.m8n8.x2.trans.shared.b16 {%0,%1},[%2];" \
                 : "=r"((r)[0]), "=r"((r)[1]) : "r"(addr))
#define MMA_BF16(d, a, b) \
    asm volatile("mma.sync.aligned.m16n8k16.row.col.f32.bf16.bf16.f32 " \
                 "{%0,%1,%2,%3},{%4,%5,%6,%7},{%8,%9},{%0,%1,%2,%3};" \
                 : "+f"((d)[0]), "+f"((d)[1]), "+f"((d)[2]), "+f"((d)[3]) \
                 : "r"((a)[0]), "r"((a)[1]), "r"((a)[2]), "r"((a)[3]), \
                   "r"((b)[0]), "r"((b)[1]))

// ---------------- bf16-split tensor GEMM: out = in @ W ----------------------
// BM=128 BN=96 BK=16, 256 threads = 8 warps (4M x 2N), warp tile 32x48.
// Split: v = hi + lo (both bf16); C = Ah*Bh + Ah*Bl + Al*Bh (fp32 accum).
// Epilogue: g_h = acc; g_agg = acc * dis^2 (self-loop init).
// A smem rows padded to 24 halves (48B) -> conflict-free ldmatrix.
// B smem rows padded to 104 halves (208B) -> conflict-free ldmatrix.trans.
template <int K, bool RELU_BIAS, bool IN_IS_AGG>
__global__ void __launch_bounds__(256, 2)
k_gemm(const float* __restrict__ in, const float* __restrict__ W,
       const float* __restrict__ bias)
{
    __shared__ __nv_bfloat16 Ah[128 * 24], Al[128 * 24];
    __shared__ __nv_bfloat16 Bh[16 * 104], Bl[16 * 104];
    __shared__ float bs[DH];

    const int tid  = threadIdx.x;
    const int lane = tid & 31;
    const int wid  = tid >> 5;
    const int wm   = wid & 3;          // 4 warps along M: 32 rows each
    const int wn   = wid >> 2;         // 2 warps along N: 48 cols each
    const int r0   = blockIdx.x * 128;
    const int gidx = lane >> 2;        // group id 0..7
    const int tidx = lane & 3;         // 0..3

    const float* __restrict__ src_in = IN_IS_AGG ? (const float*)g_agg : in;

    if (RELU_BIAS) { if (tid < DH) bs[tid] = bias[tid]; }

    float acc[2][6][4];
#pragma unroll
    for (int mt = 0; mt < 2; mt++)
#pragma unroll
        for (int nt = 0; nt < 6; nt++)
#pragma unroll
            for (int q = 0; q < 4; q++) acc[mt][nt][q] = 0.0f;

    // precomputed ldmatrix smem addresses (constant across stages)
    // A: lane -> row base_m + (lane&15), col (lane>>4)*8
    unsigned a_addr[2][2];   // [mt][hi/lo]
#pragma unroll
    for (int mt = 0; mt < 2; mt++) {
        int row = wm * 32 + mt * 16 + (lane & 15);
        int col = (lane >> 4) * 8;
        a_addr[mt][0] = smem_u32(&Ah[row * 24 + col]);
        a_addr[mt][1] = smem_u32(&Al[row * 24 + col]);
    }
    // B: lanes 0-15 -> k row (lane&15), col base_n (lanes>=16 addr ignored)
    unsigned b_addr[6][2];
#pragma unroll
    for (int nt = 0; nt < 6; nt++) {
        int krow  = lane & 15;
        int cbase = wn * 48 + nt * 8;
        b_addr[nt][0] = smem_u32(&Bh[krow * 104 + cbase]);
        b_addr[nt][1] = smem_u32(&Bl[krow * 104 + cbase]);
    }

    const int nstage = (K + 15) / 16;
    for (int s = 0; s < nstage; s++) {
        const int k0 = s * 16;
        __syncthreads();
        // ---- stage A: 128 rows x 16 k as 512 float4 quads
        for (int idx = tid; idx < 512; idx += 256) {
            int row = idx >> 2, q = idx & 3;
            int gr = r0 + row, gk = k0 + q * 4;
            float4 v = make_float4(0.f, 0.f, 0.f, 0.f);
            if (gr < NN && gk + 4 <= K)
                v = *reinterpret_cast<const float4*>(src_in + (size_t)gr * K + gk);
            float e[4] = {v.x, v.y, v.z, v.w};
#pragma unroll
            for (int j = 0; j < 4; j++) {
                float f = e[j];
                if (RELU_BIAS) f = fmaxf(f + bs[gk + j], 0.0f);
                __nv_bfloat16 hi = __float2bfloat16(f);
                __nv_bfloat16 lo = __float2bfloat16(f - __bfloat162float(hi));
                Ah[row * 24 + q * 4 + j] = hi;
                Al[row * 24 + q * 4 + j] = lo;
            }
        }
        // ---- stage B: 16 k x 96 cols as 384 float4 quads
        for (int idx = tid; idx < 384; idx += 256) {
            int kk = idx / 24, c4 = idx % 24;
            int gk = k0 + kk;
            float4 v = make_float4(0.f, 0.f, 0.f, 0.f);
            if (gk < K)
                v = *reinterpret_cast<const float4*>(W + (size_t)gk * 96 + c4 * 4);
            float e[4] = {v.x, v.y, v.z, v.w};
#pragma unroll
            for (int j = 0; j < 4; j++) {
                __nv_bfloat16 hi = __float2bfloat16(e[j]);
                __nv_bfloat16 lo = __float2bfloat16(e[j] - __bfloat162float(hi));
                Bh[kk * 104 + c4 * 4 + j] = hi;
                Bl[kk * 104 + c4 * 4 + j] = lo;
            }
        }
        __syncthreads();

        // ---- fragments
        unsigned ah[2][4], al[2][4], bh[6][2], bl[6][2];
#pragma unroll
        for (int mt = 0; mt < 2; mt++) {
            LDSM_X4(ah[mt], a_addr[mt][0]);
            LDSM_X4(al[mt], a_addr[mt][1]);
        }
#pragma unroll
        for (int nt = 0; nt < 6; nt++) {
            LDSM_X2_T(bh[nt], b_addr[nt][0]);
            LDSM_X2_T(bl[nt], b_addr[nt][1]);
        }
        // ---- 3-term split product
#pragma unroll
        for (int mt = 0; mt < 2; mt++)
#pragma unroll
            for (int nt = 0; nt < 6; nt++) {
                MMA_BF16(acc[mt][nt], ah[mt], bh[nt]);
                MMA_BF16(acc[mt][nt], ah[mt], bl[nt]);
                MMA_BF16(acc[mt][nt], al[mt], bh[nt]);
            }
    }

    // ---- epilogue: c0,c1 -> (row g, col 2t,2t+1); c2,c3 -> row g+8
#pragma unroll
    for (int mt = 0; mt < 2; mt++) {
        int rbase = r0 + wm * 32 + mt * 16 + gidx;
#pragma unroll
        for (int half = 0; half < 2; half++) {
            int r = rbase + half * 8;
            if (r >= NN) continue;
            float ds = g_dis[r];
            float d2 = ds * ds;
#pragma unroll
            for (int nt = 0; nt < 6; nt++) {
                int c = wn * 48 + nt * 8 + tidx * 2;
                float v0 = acc[mt][nt][half * 2 + 0];
                float v1 = acc[mt][nt][half * 2 + 1];
                size_t o = (size_t)r * 96 + c;
                *reinterpret_cast<float2*>(g_h + o)   = make_float2(v0, v1);
                *reinterpret_cast<float2*>(g_agg + o) = make_float2(v0 * d2, v1 * d2);
            }
        }
    }
}

// ---------------- edge scatter: agg[dst] += h[src] * dis[src]*dis[dst] ------
__global__ void __launch_bounds__(192)
k_scatter(const int* __restrict__ src, const int* __restrict__ dst)
{
    int e = blockIdx.x * 8 + threadIdx.y;
    if (e >= EE) return;
    int s = src[e], d = dst[e];
    float nrm = g_dis[s] * g_dis[d];
    int c = threadIdx.x * 4;
    float4 v = *reinterpret_cast<const float4*>(g_h + (size_t)s * 96 + c);
    float4 m = make_float4(v.x * nrm, v.y * nrm, v.z * nrm, v.w * nrm);
    float* p = g_agg + (size_t)d * 96 + c;
    asm volatile("red.global.add.v4.f32 [%0], {%1, %2, %3, %4};"
                 :: "l"(__cvta_generic_to_global(p)),
                    "f"(m.x), "f"(m.y), "f"(m.z), "f"(m.w) : "memory");
}

// ---------------- pooling ----------------------------------------------------
__global__ void __launch_bounds__(96)
k_pool(const float* __restrict__ b2, const int* __restrict__ batch)
{
    int c  = threadIdx.x;
    int r0 = blockIdx.x * 64;
    int re = min(r0 + 64, NN);
    if (r0 >= NN) return;
    float bb = b2[c];
    float acc = 0.0f;
    int cur = batch[r0];
    int run = 0;
    for (int r = r0; r < re; r++) {
        int g = batch[r];
        if (g != cur) {
            atomicAdd(&g_pool[cur * DH + c], acc);
            if (c == 0) atomicAdd(&g_cnt[cur], (float)run);
            acc = 0.0f; run = 0; cur = g;
        }
        acc += fmaxf(g_agg[(size_t)r * 96 + c] + bb, 0.0f);
        run++;
    }
    atomicAdd(&g_pool[cur * DH + c], acc);
    if (c == 0) atomicAdd(&g_cnt[cur], (float)run);
}

// ---------------- head -------------------------------------------------------
__global__ void k_fc(const float* __restrict__ Wfc, const float* __restrict__ bfc,
                     float* __restrict__ out)
{
    int t = threadIdx.x;
    if (t >= GG * DOUT) return;
    int g = t >> 1, o = t & 1;
    float cn = fmaxf(g_cnt[g], 1.0f);
    float s = bfc[o];
    for (int c = 0; c < DH; c++)
        s += (g_pool[g * DH + c] / cn) * Wfc[c * DOUT + o];
    out[g * DOUT + o] = s;
}

// ---------------- launch ------------------------------------------------------
extern "C" void kernel_launch(void* const* d_in, const int* in_sizes, int n_in,
                              void* d_out, int out_size)
{
    const float* x    = (const float*)d_in[0];
    const float* W1   = (const float*)d_in[1];
    const float* b1   = (const float*)d_in[2];
    const float* W2   = (const float*)d_in[3];
    const float* b2   = (const float*)d_in[4];
    const float* Wfc  = (const float*)d_in[5];
    const float* bfc  = (const float*)d_in[6];
    const int*   src  = (const int*)d_in[7];
    const int*   dst  = (const int*)d_in[8];
    const int*   batch= (const int*)d_in[9];
    float* out = (float*)d_out;

    const int nb_n = (NN + 255) / 256;
    const int nb_e = (EE + 255) / 256;
    const int nb_g = (NN + 127) / 128;
    const int nb_p = (NN + 63) / 64;

    k_deg_init  <<<nb_n, 256>>>();
    k_deg_count <<<nb_e, 256>>>(dst);
    k_deg_finish<<<nb_n, 256>>>();

    // layer 1: h1 = x@W1; agg1 = h1*dis^2
    k_gemm<DIN, false, false><<<nb_g, 256>>>(x, W1, b1);
    k_scatter<<<(EE + 7) / 8, dim3(24, 8)>>>(src, dst);

    // layer 2: h2 = relu(agg1+b1)@W2; agg2 = h2*dis^2
    k_gemm<DH, true, true><<<nb_g, 256>>>(nullptr, W2, b1);
    k_scatter<<<(EE + 7) / 8, dim3(24, 8)>>>(src, dst);

    k_pool<<<nb_p, 96>>>(b2, batch);
    k_fc  <<<1, 128>>>(Wfc, bfc, out);
}

// round 5
// speedup vs baseline: 1.6046x; 1.2891x over previous
#include <cuda_runtime.h>
#include <cuda_bf16.h>
#include <math.h>

#define NN    50000
#define EE    800000
#define DIN   300
#define DH    96
#define DOUT  2
#define GG    64

// ---------------- scratch (device globals; no allocation allowed) -----------
__device__ float g_dis[NN];
__device__ float g_h  [(size_t)NN * DH];
__device__ float g_agg[(size_t)NN * DH];
__device__ float g_pool[GG * DH];
__device__ float g_cnt [GG];
// pre-split weights (bf16 hi/lo), written once per launch by k_wsplit
__device__ __nv_bfloat16 g_W1h[DIN * DH], g_W1l[DIN * DH];
__device__ __nv_bfloat16 g_W2h[DH * DH],  g_W2l[DH * DH];

// ---------------- degree ----------------------------------------------------
__global__ void k_deg_init() {
    int i = blockIdx.x * blockDim.x + threadIdx.x;
    if (i < NN) g_dis[i] = 1.0f;            // +1 self loop
}
__global__ void k_deg_count(const int* __restrict__ dst) {
    int e = blockIdx.x * blockDim.x + threadIdx.x;
    if (e < EE) atomicAdd(&g_dis[dst[e]], 1.0f);
}
__global__ void k_deg_finish() {
    int i = blockIdx.x * blockDim.x + threadIdx.x;
    if (i < NN) g_dis[i] = rsqrtf(g_dis[i]);
    if (i < GG * DH) g_pool[i] = 0.0f;
    if (i < GG)      g_cnt[i]  = 0.0f;
}

// ---------------- weight split: W -> bf16 hi + bf16 lo ----------------------
__global__ void k_wsplit(const float* __restrict__ W1, const float* __restrict__ W2) {
    int i = blockIdx.x * blockDim.x + threadIdx.x;
    if (i < DIN * DH) {
        float f = W1[i];
        __nv_bfloat16 hi = __float2bfloat16(f);
        g_W1h[i] = hi;
        g_W1l[i] = __float2bfloat16(f - __bfloat162float(hi));
    }
    if (i < DH * DH) {
        float f = W2[i];
        __nv_bfloat16 hi = __float2bfloat16(f);
        g_W2h[i] = hi;
        g_W2l[i] = __float2bfloat16(f - __bfloat162float(hi));
    }
}

// ---------------- mma helpers ------------------------------------------------
__device__ __forceinline__ unsigned smem_u32(const void* p) {
    return (unsigned)__cvta_generic_to_shared(p);
}
#define LDSM_X4(r, addr) \
    asm volatile("ldmatrix.sync.aligned.m8n8.x4.shared.b16 {%0,%1,%2,%3},[%4];" \
                 : "=r"((r)[0]), "=r"((r)[1]), "=r"((r)[2]), "=r"((r)[3]) : "r"(addr))
#define LDSM_X2_T(r, addr) \
    asm volatile("ldmatrix.sync.aligned.m8n8.x2.trans.shared.b16 {%0,%1},[%2];" \
                 : "=r"((r)[0]), "=r"((r)[1]) : "r"(addr))
#define MMA_BF16(d, a, b) \
    asm volatile("mma.sync.aligned.m16n8k16.row.col.f32.bf16.bf16.f32 " \
                 "{%0,%1,%2,%3},{%4,%5,%6,%7},{%8,%9},{%0,%1,%2,%3};" \
                 : "+f"((d)[0]), "+f"((d)[1]), "+f"((d)[2]), "+f"((d)[3]) \
                 : "r"((a)[0]), "r"((a)[1]), "r"((a)[2]), "r"((a)[3]), \
                   "r"((b)[0]), "r"((b)[1]))

// ---------------- pipelined bf16-split tensor GEMM: out = in @ W ------------
// BM=128 BN=96 BK=16, 256 thr = 8 warps (4M x 2N), warp tile 32x48.
// Double-buffered smem, register prefetch, 1 barrier/stage.
// Epilogue: g_h = acc; g_agg = acc * dis^2.
template <int K, bool RELU_BIAS, bool IN_IS_AGG, int WSEL>
__global__ void __launch_bounds__(256, 2)
k_gemm(const float* __restrict__ in, const float* __restrict__ bias)
{
    __shared__ __nv_bfloat16 Ah[2][128 * 24], Al[2][128 * 24];   // 48B rows
    __shared__ __nv_bfloat16 Bh[2][16 * 104], Bl[2][16 * 104];   // 208B rows
    __shared__ float bs[DH];

    const int tid  = threadIdx.x;
    const int lane = tid & 31;
    const int wid  = tid >> 5;
    const int wm   = wid & 3;
    const int wn   = wid >> 2;
    const int r0   = blockIdx.x * 128;
    const int gidx = lane >> 2;
    const int tidx = lane & 3;

    const float* __restrict__ src_in = IN_IS_AGG ? (const float*)g_agg : in;
    const uint4* __restrict__ Wh4 =
        (const uint4*)(WSEL == 1 ? (const void*)g_W1h : (const void*)g_W2h);
    const uint4* __restrict__ Wl4 =
        (const uint4*)(WSEL == 1 ? (const void*)g_W1l : (const void*)g_W2l);

    if (RELU_BIAS) { if (tid < DH) bs[tid] = bias[tid]; }

    float acc[2][6][4];
#pragma unroll
    for (int mt = 0; mt < 2; mt++)
#pragma unroll
        for (int nt = 0; nt < 6; nt++)
#pragma unroll
            for (int q = 0; q < 4; q++) acc[mt][nt][q] = 0.0f;

    // ldmatrix base addresses (buffer 0)
    unsigned a_h0[2], a_l0[2];
#pragma unroll
    for (int mt = 0; mt < 2; mt++) {
        int row = wm * 32 + mt * 16 + (lane & 15);
        int col = (lane >> 4) * 8;
        a_h0[mt] = smem_u32(&Ah[0][row * 24 + col]);
        a_l0[mt] = smem_u32(&Al[0][row * 24 + col]);
    }
    unsigned b_h0[6], b_l0[6];
#pragma unroll
    for (int nt = 0; nt < 6; nt++) {
        int krow  = lane & 15;
        int cbase = wn * 48 + nt * 8;
        b_h0[nt] = smem_u32(&Bh[0][krow * 104 + cbase]);
        b_l0[nt] = smem_u32(&Bl[0][krow * 104 + cbase]);
    }
    const unsigned A_STRIDE = 128 * 24 * 2;   // bytes per A buffer
    const unsigned B_STRIDE = 16 * 104 * 2;   // bytes per B buffer

    // ---- prefetch helpers (A: 2 float4/thread; B: up to 2 uint4/thread) ----
    float4 pa[2];
    uint4  pb[2];

    auto load_stage = [&](int k0) {
#pragma unroll
        for (int t = 0; t < 2; t++) {
            int idx = tid + t * 256;          // < 512
            int row = idx >> 2, q = idx & 3;
            int gr = r0 + row, gk = k0 + q * 4;
            pa[t] = make_float4(0.f, 0.f, 0.f, 0.f);
            if (gr < NN && gk + 4 <= K)
                pa[t] = *reinterpret_cast<const float4*>(src_in + (size_t)gr * K + gk);
        }
#pragma unroll
        for (int t = 0; t < 2; t++) {
            int idx = tid + t * 256;
            if (idx < 384) {
                int half = (idx >= 192);
                int j  = idx - half * 192;
                int kk = j / 12, c = j % 12;
                int gk = k0 + kk;
                pb[t] = make_uint4(0u, 0u, 0u, 0u);
                if (gk < K)
                    pb[t] = (half ? Wl4 : Wh4)[gk * 12 + c];
            }
        }
    };

    auto store_stage = [&](int buf, int k0) {
#pragma unroll
        for (int t = 0; t < 2; t++) {
            int idx = tid + t * 256;
            int row = idx >> 2, q = idx & 3;
            float e[4] = {pa[t].x, pa[t].y, pa[t].z, pa[t].w};
            unsigned hp[2], lp[2];
#pragma unroll
            for (int p = 0; p < 2; p++) {
                float f0 = e[p * 2], f1 = e[p * 2 + 1];
                if (RELU_BIAS) {
                    int gk = k0 + q * 4 + p * 2;
                    f0 = fmaxf(f0 + bs[gk], 0.0f);
                    f1 = fmaxf(f1 + bs[gk + 1], 0.0f);
                }
                __nv_bfloat162 h2 = make_bfloat162(__float2bfloat16(f0),
                                                   __float2bfloat16(f1));
                __nv_bfloat162 l2 = make_bfloat162(
                    __float2bfloat16(f0 - __bfloat162float(h2.x)),
                    __float2bfloat16(f1 - __bfloat162float(h2.y)));
                hp[p] = *reinterpret_cast<unsigned*>(&h2);
                lp[p] = *reinterpret_cast<unsigned*>(&l2);
            }
            *reinterpret_cast<uint2*>(&Ah[buf][row * 24 + q * 4]) = make_uint2(hp[0], hp[1]);
            *reinterpret_cast<uint2*>(&Al[buf][row * 24 + q * 4]) = make_uint2(lp[0], lp[1]);
        }
#pragma unroll
        for (int t = 0; t < 2; t++) {
            int idx = tid + t * 256;
            if (idx < 384) {
                int half = (idx >= 192);
                int j  = idx - half * 192;
                int kk = j / 12, c = j % 12;
                __nv_bfloat16* dstp = half ? Bl[buf] : Bh[buf];
                *reinterpret_cast<uint4*>(&dstp[kk * 104 + c * 8]) = pb[t];
            }
        }
    };

    const int nstage = (K + 15) / 16;
    load_stage(0);
    __syncthreads();          // bs visible (relu path); harmless otherwise

    for (int s = 0; s < nstage; s++) {
        const int buf = s & 1;
        store_stage(buf, s * 16);
        __syncthreads();
        if (s + 1 < nstage) load_stage((s + 1) * 16);

        const unsigned ao = buf * A_STRIDE, bo = buf * B_STRIDE;
        unsigned ah[2][4], al[2][4], bh[6][2], bl[6][2];
#pragma unroll
        for (int mt = 0; mt < 2; mt++) {
            LDSM_X4(ah[mt], a_h0[mt] + ao);
            LDSM_X4(al[mt], a_l0[mt] + ao);
        }
#pragma unroll
        for (int nt = 0; nt < 6; nt++) {
            LDSM_X2_T(bh[nt], b_h0[nt] + bo);
            LDSM_X2_T(bl[nt], b_l0[nt] + bo);
        }
#pragma unroll
        for (int mt = 0; mt < 2; mt++)
#pragma unroll
            for (int nt = 0; nt < 6; nt++) {
                MMA_BF16(acc[mt][nt], ah[mt], bh[nt]);
                MMA_BF16(acc[mt][nt], ah[mt], bl[nt]);
                MMA_BF16(acc[mt][nt], al[mt], bh[nt]);
            }
    }

    // ---- epilogue
#pragma unroll
    for (int mt = 0; mt < 2; mt++) {
        int rbase = r0 + wm * 32 + mt * 16 + gidx;
#pragma unroll
        for (int half = 0; half < 2; half++) {
            int r = rbase + half * 8;
            if (r >= NN) continue;
            float ds = g_dis[r];
            float d2 = ds * ds;
#pragma unroll
            for (int nt = 0; nt < 6; nt++) {
                int c = wn * 48 + nt * 8 + tidx * 2;
                float v0 = acc[mt][nt][half * 2 + 0];
                float v1 = acc[mt][nt][half * 2 + 1];
                size_t o = (size_t)r * 96 + c;
                *reinterpret_cast<float2*>(g_h + o)   = make_float2(v0, v1);
                *reinterpret_cast<float2*>(g_agg + o) = make_float2(v0 * d2, v1 * d2);
            }
        }
    }
}

// ---------------- edge scatter: agg[dst] += h[src] * dis[src]*dis[dst] ------
__global__ void __launch_bounds__(192)
k_scatter(const int* __restrict__ src, const int* __restrict__ dst)
{
    int e = blockIdx.x * 8 + threadIdx.y;
    if (e >= EE) return;
    int s = src[e], d = dst[e];
    float nrm = g_dis[s] * g_dis[d];
    int c = threadIdx.x * 4;
    float4 v = *reinterpret_cast<const float4*>(g_h + (size_t)s * 96 + c);
    float4 m = make_float4(v.x * nrm, v.y * nrm, v.z * nrm, v.w * nrm);
    float* p = g_agg + (size_t)d * 96 + c;
    asm volatile("red.global.add.v4.f32 [%0], {%1, %2, %3, %4};"
                 :: "l"(__cvta_generic_to_global(p)),
                    "f"(m.x), "f"(m.y), "f"(m.z), "f"(m.w) : "memory");
}

// ---------------- pooling ----------------------------------------------------
__global__ void __launch_bounds__(96)
k_pool(const float* __restrict__ b2, const int* __restrict__ batch)
{
    int c  = threadIdx.x;
    int r0 = blockIdx.x * 64;
    int re = min(r0 + 64, NN);
    if (r0 >= NN) return;
    float bb = b2[c];
    float acc = 0.0f;
    int cur = batch[r0];
    int run = 0;
    for (int r = r0; r < re; r++) {
        int g = batch[r];
        if (g != cur) {
            atomicAdd(&g_pool[cur * DH + c], acc);
            if (c == 0) atomicAdd(&g_cnt[cur], (float)run);
            acc = 0.0f; run = 0; cur = g;
        }
        acc += fmaxf(g_agg[(size_t)r * 96 + c] + bb, 0.0f);
        run++;
    }
    atomicAdd(&g_pool[cur * DH + c], acc);
    if (c == 0) atomicAdd(&g_cnt[cur], (float)run);
}

// ---------------- head -------------------------------------------------------
__global__ void k_fc(const float* __restrict__ Wfc, const float* __restrict__ bfc,
                     float* __restrict__ out)
{
    int t = threadIdx.x;
    if (t >= GG * DOUT) return;
    int g = t >> 1, o = t & 1;
    float cn = fmaxf(g_cnt[g], 1.0f);
    float s = bfc[o];
    for (int c = 0; c < DH; c++)
        s += (g_pool[g * DH + c] / cn) * Wfc[c * DOUT + o];
    out[g * DOUT + o] = s;
}

// ---------------- launch ------------------------------------------------------
extern "C" void kernel_launch(void* const* d_in, const int* in_sizes, int n_in,
                              void* d_out, int out_size)
{
    const float* x    = (const float*)d_in[0];
    const float* W1   = (const float*)d_in[1];
    const float* b1   = (const float*)d_in[2];
    const float* W2   = (const float*)d_in[3];
    const float* b2   = (const float*)d_in[4];
    const float* Wfc  = (const float*)d_in[5];
    const float* bfc  = (const float*)d_in[6];
    const int*   src  = (const int*)d_in[7];
    const int*   dst  = (const int*)d_in[8];
    const int*   batch= (const int*)d_in[9];
    float* out = (float*)d_out;

    const int nb_n = (NN + 255) / 256;
    const int nb_e = (EE + 255) / 256;
    const int nb_g = (NN + 127) / 128;
    const int nb_p = (NN + 63) / 64;

    k_wsplit    <<<(DIN * DH + 255) / 256, 256>>>(W1, W2);
    k_deg_init  <<<nb_n, 256>>>();
    k_deg_count <<<nb_e, 256>>>(dst);
    k_deg_finish<<<nb_n, 256>>>();

    // layer 1: h1 = x@W1; agg1 = h1*dis^2
    k_gemm<DIN, false, false, 1><<<nb_g, 256>>>(x, b1);
    k_scatter<<<(EE + 7) / 8, dim3(24, 8)>>>(src, dst);

    // layer 2: h2 = relu(agg1+b1)@W2; agg2 = h2*dis^2
    k_gemm<DH, true, true, 2><<<nb_g, 256>>>(nullptr, b1);
    k_scatter<<<(EE + 7) / 8, dim3(24, 8)>>>(src, dst);

    k_pool<<<nb_p, 96>>>(b2, batch);
    k_fc  <<<1, 128>>>(Wfc, bfc, out);
}